// round 16
// baseline (speedup 1.0000x reference)
#include <cuda_runtime.h>
#include <cstdint>

// FeatureRecalibration3D: x[2,64,64,96,96] fp32
// z[b,c] = mean(depthwise_conv3x3x3(x,pad=1)) via inclusion-exclusion:
//   sum(conv) = Wall*T - faces + edges - corners   (conv never materialized)
// gate = sigmoid(fc2 . leakyrelu(fc1 . z + b1) + b2);  out = x * gate[b,c]
// R16 experiment: scale pass uses EXACTLY one residency (1184 blocks) with an
// even static partition -> zero wave quantization. Reduce/MLP/PDL unchanged.

#define B_  2
#define C_  64
#define D_  64
#define H_  96
#define W_  96
#define DHW_ 589824
#define NBC 128
#define NF4 (DHW_ / 4)              // 147456 float4 per (b,c) slab
#define TOTAL_F4 ((size_t)NBC * NF4) // 18,874,368
#define NEG_SLOPE 0.01f

#define SPLIT 32                    // bulk parts per slab
#define F4_PER_PART (NF4 / SPLIT)   // 4608
#define THREADS 256
#define ITERS (F4_PER_PART / THREADS) // 18

#define NBND (NBC * 2)              // 2 boundary blocks per slab
#define NBLK (NBND + NBC * SPLIT)

#define SC_BLOCKS 1184              // 148 SMs x 8 resident = single wave
#define SC_THREADS 256

__device__ float g_T [NBC * SPLIT];
__device__ float g_W0[NBC * SPLIT];
__device__ float g_WL[NBC * SPLIT];
__device__ float g_bnd[NBC * 24];
__device__ float g_gate[NBC];

// g_bnd layout per slab:
//  0:E_d0h0 1:E_d0hL 2:E_dLh0 3:E_dLhL   4:E_d0w0 5:E_d0wL 6:E_dLw0 7:E_dLwL
//  8:E_h0w0 9:E_h0wL 10:E_hLw0 11:E_hLwL
// 12..19: corners d0h0w0,d0h0wL,d0hLw0,d0hLwL,dLh0w0,dLh0wL,dLhLw0,dLhLwL
// 20:S_d0 21:S_dL 22:F_h0 23:F_hL

__device__ __forceinline__ void addf32x2(unsigned long long& a, unsigned long long b) {
    asm("add.rn.f32x2 %0, %0, %1;" : "+l"(a) : "l"(b));
}
__device__ __forceinline__ void mulf32x2(unsigned long long& a, unsigned long long b) {
    asm("mul.rn.f32x2 %0, %0, %1;" : "+l"(a) : "l"(b));
}
__device__ __forceinline__ float f32lo(unsigned long long v) {
    return __uint_as_float((unsigned)(v & 0xffffffffull));
}
__device__ __forceinline__ float f32hi(unsigned long long v) {
    return __uint_as_float((unsigned)(v >> 32));
}
__device__ __forceinline__ ulonglong2 ldnc_u64x2(const ulonglong2* p) {
    ulonglong2 v;
    asm("ld.global.nc.v2.u64 {%0,%1}, [%2];" : "=l"(v.x), "=l"(v.y) : "l"(p));
    return v;
}
__device__ __forceinline__ void stcs_u64x2(ulonglong2* p, ulonglong2 v) {
    asm("st.global.cs.v2.u64 [%0], {%1,%2};" :: "l"(p), "l"(v.x), "l"(v.y) : "memory");
}

// ================= Pass A: reduce (bulk + boundary blocks) =================
__global__ __launch_bounds__(THREADS, 8)
void fused_reduce(const float* __restrict__ x) {
    const int tid = threadIdx.x;
    __shared__ float warp_s[8 * 3];
    __shared__ float bsum[24];

    if (blockIdx.x >= NBND) {
        // ---------- bulk block: plain sum + w-column sums ----------
        const int bid  = blockIdx.x - NBND;
        const int slab = bid / SPLIT;
        const int part = bid % SPLIT;
        const ulonglong2* xp =
            (const ulonglong2*)x + (size_t)slab * NF4 + part * F4_PER_PART + tid;

        float mw0[3], mwL[3];
#pragma unroll
        for (int r = 0; r < 3; ++r) {
            int off = (tid + 16 * r) % 24;
            mw0[r] = (off == 0)  ? 1.0f : 0.0f;
            mwL[r] = (off == 23) ? 1.0f : 0.0f;
        }

        unsigned long long a01 = 0ull, a23 = 0ull;
        float w0acc = 0.f, wLacc = 0.f;
#pragma unroll
        for (int it = 0; it < ITERS; ++it) {
            ulonglong2 v = ldnc_u64x2(xp + it * THREADS);
            addf32x2(a01, v.x);
            addf32x2(a23, v.y);
            w0acc = fmaf(f32lo(v.x), mw0[it % 3], w0acc);
            wLacc = fmaf(f32hi(v.y), mwL[it % 3], wLacc);
        }
        float T = (f32lo(a01) + f32hi(a01)) + (f32lo(a23) + f32hi(a23));

        const int lane = tid & 31, wid = tid >> 5;
#pragma unroll
        for (int o = 16; o > 0; o >>= 1) {
            T     += __shfl_down_sync(0xFFFFFFFFu, T, o);
            w0acc += __shfl_down_sync(0xFFFFFFFFu, w0acc, o);
            wLacc += __shfl_down_sync(0xFFFFFFFFu, wLacc, o);
        }
        if (lane == 0) {
            warp_s[wid * 3 + 0] = T;
            warp_s[wid * 3 + 1] = w0acc;
            warp_s[wid * 3 + 2] = wLacc;
        }
        __syncthreads();
        if (tid == 0) {
            float t = 0.f, a = 0.f, b = 0.f;
#pragma unroll
            for (int w = 0; w < 8; ++w) {
                t += warp_s[w * 3 + 0];
                a += warp_s[w * 3 + 1];
                b += warp_s[w * 3 + 2];
            }
            g_T [slab * SPLIT + part] = t;
            g_W0[slab * SPLIT + part] = a;
            g_WL[slab * SPLIT + part] = b;
        }
        return;
    }

    // ---------- boundary blocks: 2 per slab ----------
    const int slab = blockIdx.x >> 1;
    const int typ  = blockIdx.x & 1;       // 0: d-faces, 1: h-faces
    const float4* xs = (const float4*)x + (size_t)slab * NF4;

    if (tid < 24) bsum[tid] = 0.f;
    __syncthreads();

    if (typ == 0) {
        // d-faces: full 96x96 planes at d=0 and d=63 (2304 f4 each)
        float s_d0 = 0.f, s_dL = 0.f;
#pragma unroll
        for (int p = 0; p < 2; ++p) {
            const float4* pb = xs + (p ? 63 * 2304 : 0);
            float sp = 0.f;
            for (int i = 0; i < 9; ++i) {
                int idx = i * 256 + tid;
                float4 v = __ldg(pb + idx);
                int h = idx / 24, w4 = idx - h * 24;
                float s4 = (v.x + v.y) + (v.z + v.w);
                sp += s4;
                bool h0 = (h == 0), hL = (h == 95);
                if (h0) atomicAdd(&bsum[p ? 2 : 0], s4);
                if (hL) atomicAdd(&bsum[p ? 3 : 1], s4);
                if (w4 == 0) {
                    atomicAdd(&bsum[p ? 6 : 4], v.x);
                    if (h0) atomicAdd(&bsum[12 + p * 4 + 0], v.x);
                    if (hL) atomicAdd(&bsum[12 + p * 4 + 2], v.x);
                }
                if (w4 == 23) {
                    atomicAdd(&bsum[p ? 7 : 5], v.w);
                    if (h0) atomicAdd(&bsum[12 + p * 4 + 1], v.w);
                    if (hL) atomicAdd(&bsum[12 + p * 4 + 3], v.w);
                }
            }
            if (p) s_dL = sp; else s_d0 = sp;
        }
#pragma unroll
        for (int o = 16; o > 0; o >>= 1) {
            s_d0 += __shfl_down_sync(0xFFFFFFFFu, s_d0, o);
            s_dL += __shfl_down_sync(0xFFFFFFFFu, s_dL, o);
        }
        if ((tid & 31) == 0) {
            atomicAdd(&bsum[20], s_d0);
            atomicAdd(&bsum[21], s_dL);
        }
        __syncthreads();
        if (tid < 22 && tid != 8 && tid != 9 && tid != 10 && tid != 11)
            g_bnd[slab * 24 + tid] = bsum[tid];
    } else {
        // h-faces: rows h=0 / h=95 for all d (1536 f4 each)
        float f_h0 = 0.f, f_hL = 0.f;
#pragma unroll
        for (int q = 0; q < 2; ++q) {
            float fq = 0.f;
            for (int i = 0; i < 6; ++i) {
                int idx = i * 256 + tid;
                int d = idx / 24, w4 = idx - d * 24;
                float4 v = __ldg(xs + d * 2304 + (q ? 2280 : 0) + w4);
                fq += (v.x + v.y) + (v.z + v.w);
                if (w4 == 0)  atomicAdd(&bsum[8 + 2 * q], v.x);
                if (w4 == 23) atomicAdd(&bsum[9 + 2 * q], v.w);
            }
            if (q) f_hL = fq; else f_h0 = fq;
        }
#pragma unroll
        for (int o = 16; o > 0; o >>= 1) {
            f_h0 += __shfl_down_sync(0xFFFFFFFFu, f_h0, o);
            f_hL += __shfl_down_sync(0xFFFFFFFFu, f_hL, o);
        }
        if ((tid & 31) == 0) {
            atomicAdd(&bsum[22], f_h0);
            atomicAdd(&bsum[23], f_hL);
        }
        __syncthreads();
        if ((tid >= 8 && tid < 12) || tid == 22 || tid == 23)
            g_bnd[slab * 24 + tid] = bsum[tid];
    }
}

// ================= Pass B: combine sums + MLP + sigmoid gate (PDL) =================
__global__ __launch_bounds__(128)
void mlp_kernel(const float* __restrict__ dw_w,
                const float* __restrict__ fc1_w,
                const float* __restrict__ fc1_b,
                const float* __restrict__ fc2_w,
                const float* __restrict__ fc2_b) {
    const int tid = threadIdx.x;        // tid == slab == b*64 + c
    const int c = tid & (C_ - 1);
    __shared__ float z_s[NBC];
    __shared__ float h_s[B_ * 8];

    // dependency-free preamble: load the small weights while reduce drains
    const float* wc = dw_w + c * 27;
    float w[27];
#pragma unroll
    for (int t = 0; t < 27; ++t) w[t] = wc[t];

    float Wall = 0.f;
    float Wd[3] = {0,0,0}, Wh[3] = {0,0,0}, Ww[3] = {0,0,0};
    float Wdh[3][3] = {}, Wdw[3][3] = {}, Whw[3][3] = {};
#pragma unroll
    for (int kd = 0; kd < 3; ++kd)
#pragma unroll
        for (int kh = 0; kh < 3; ++kh)
#pragma unroll
            for (int kw = 0; kw < 3; ++kw) {
                float v = w[kd * 9 + kh * 3 + kw];
                Wall += v;
                Wd[kd] += v; Wh[kh] += v; Ww[kw] += v;
                Wdh[kd][kh] += v; Wdw[kd][kw] += v; Whw[kh][kw] += v;
            }
    const float b1 = (tid < B_ * 8) ? fc1_b[tid % 8] : 0.f;
    float w1row[C_ / 4][4];
    if (tid < B_ * 8) {
        const int i = tid % 8;
#pragma unroll
        for (int cc = 0; cc < C_ / 4; ++cc) {
            float4 v = __ldg((const float4*)(fc1_w + i * C_) + cc);
            w1row[cc][0] = v.x; w1row[cc][1] = v.y;
            w1row[cc][2] = v.z; w1row[cc][3] = v.w;
        }
    }
    const float b2 = fc2_b[c];
    float w2row[8];
#pragma unroll
    for (int i = 0; i < 8; ++i) w2row[i] = fc2_w[c * 8 + i];

    // wait for fused_reduce results
    cudaGridDependencySynchronize();

    float T = 0.f, Fw0 = 0.f, FwL = 0.f;
#pragma unroll
    for (int p = 0; p < SPLIT; ++p) {
        T   += g_T [tid * SPLIT + p];
        Fw0 += g_W0[tid * SPLIT + p];
        FwL += g_WL[tid * SPLIT + p];
    }
    float bv[24];
#pragma unroll
    for (int k = 0; k < 24; ++k) bv[k] = g_bnd[tid * 24 + k];

    float zs = Wall * T
        - Wd[2] * bv[20] - Wd[0] * bv[21]
        - Wh[2] * bv[22] - Wh[0] * bv[23]
        - Ww[2] * Fw0    - Ww[0] * FwL
        + Wdh[2][2]*bv[0] + Wdh[2][0]*bv[1] + Wdh[0][2]*bv[2] + Wdh[0][0]*bv[3]
        + Wdw[2][2]*bv[4] + Wdw[2][0]*bv[5] + Wdw[0][2]*bv[6] + Wdw[0][0]*bv[7]
        + Whw[2][2]*bv[8] + Whw[2][0]*bv[9] + Whw[0][2]*bv[10] + Whw[0][0]*bv[11]
        - w[26]*bv[12] - w[24]*bv[13] - w[20]*bv[14] - w[18]*bv[15]
        - w[8] *bv[16] - w[6] *bv[17] - w[2] *bv[18] - w[0] *bv[19];

    z_s[tid] = zs * (1.0f / (float)DHW_);
    __syncthreads();

    if (tid < B_ * 8) {
        const int b = tid / 8;
        float h = b1;
#pragma unroll
        for (int cc = 0; cc < C_ / 4; ++cc)
#pragma unroll
            for (int j = 0; j < 4; ++j)
                h += z_s[b * C_ + cc * 4 + j] * w1row[cc][j];
        h_s[tid] = (h >= 0.f) ? h : NEG_SLOPE * h;
    }
    __syncthreads();

    const int b = tid / C_;
    float g = b2;
#pragma unroll
    for (int i = 0; i < 8; ++i)
        g += h_s[b * 8 + i] * w2row[i];
    g_gate[tid] = 1.0f / (1.0f + __expf(-g));
    // release downstream (scale) as soon as the gate is written
    cudaTriggerProgrammaticLaunchCompletion();
}

// ===== Pass C: out = x * gate — single-wave even partition, .cs stores =====
__global__ __launch_bounds__(SC_THREADS, 8)
void scale_kernel(const float* __restrict__ x, float* __restrict__ out) {
    const unsigned bid = blockIdx.x;
    // even static partition: block owns f4 range [start, end)
    const size_t start = (size_t)bid       * TOTAL_F4 / SC_BLOCKS;
    const size_t end   = (size_t)(bid + 1) * TOTAL_F4 / SC_BLOCKS;

    const ulonglong2* xp = (const ulonglong2*)x;
    ulonglong2*       op = (ulonglong2*)out;

    cudaGridDependencySynchronize();

    size_t i = start + threadIdx.x;
    int slab = (int)(i / NF4);
    unsigned long long gg;
    asm("mov.b64 %0, {%1,%1};" : "=l"(gg) : "r"(__float_as_uint(g_gate[slab])));
    size_t slab_end = (size_t)(slab + 1) * NF4;   // refresh gate at slab crossings

    for (; i < end; i += SC_THREADS) {
        if (i >= slab_end) {
            slab = (int)(i / NF4);
            asm("mov.b64 %0, {%1,%1};" : "=l"(gg) : "r"(__float_as_uint(g_gate[slab])));
            slab_end = (size_t)(slab + 1) * NF4;
        }
        ulonglong2 v = ldnc_u64x2(xp + i);
        mulf32x2(v.x, gg);
        mulf32x2(v.y, gg);
        stcs_u64x2(op + i, v);
    }
}

extern "C" void kernel_launch(void* const* d_in, const int* in_sizes, int n_in,
                              void* d_out, int out_size) {
    const float* x     = (const float*)d_in[0];
    const float* dw_w  = (const float*)d_in[1];
    const float* fc1_w = (const float*)d_in[2];
    const float* fc1_b = (const float*)d_in[3];
    const float* fc2_w = (const float*)d_in[4];
    const float* fc2_b = (const float*)d_in[5];
    float* out = (float*)d_out;

    cudaLaunchAttribute attr[1];
    attr[0].id = cudaLaunchAttributeProgrammaticStreamSerialization;
    attr[0].val.programmaticStreamSerializationAllowed = 1;

    {
        cudaLaunchConfig_t cfg = {};
        cfg.gridDim = dim3(NBLK, 1, 1);
        cfg.blockDim = dim3(THREADS, 1, 1);
        cfg.attrs = attr;
        cfg.numAttrs = 1;
        cudaLaunchKernelEx(&cfg, fused_reduce, x);
    }
    {
        cudaLaunchConfig_t cfg = {};
        cfg.gridDim = dim3(1, 1, 1);
        cfg.blockDim = dim3(128, 1, 1);
        cfg.attrs = attr;
        cfg.numAttrs = 1;
        cudaLaunchKernelEx(&cfg, mlp_kernel, dw_w, fc1_w, fc1_b, fc2_w, fc2_b);
    }
    {
        cudaLaunchConfig_t cfg = {};
        cfg.gridDim = dim3(SC_BLOCKS, 1, 1);
        cfg.blockDim = dim3(SC_THREADS, 1, 1);
        cfg.attrs = attr;
        cfg.numAttrs = 1;
        cudaLaunchKernelEx(&cfg, scale_kernel, x, out);
    }
}

// round 17
// speedup vs baseline: 1.1133x; 1.1133x over previous
#include <cuda_runtime.h>
#include <cstdint>

// FeatureRecalibration3D: x[2,64,64,96,96] fp32  — FINAL (converged) version.
// z[b,c] = mean(depthwise_conv3x3x3(x,pad=1)) via inclusion-exclusion:
//   sum(conv) = Wall*T - faces + edges - corners   (conv never materialized)
// gate = sigmoid(fc2 . leakyrelu(fc1 . z + b1) + b2);  out = x * gate[b,c]
// Proven elements: packed f32x2 math; fully-unrolled immediate-offset streams
// (R16 showed dynamic-bound loops cost ~16us); reversed-order scale (+7us L2
// handoff); .cs stores; PDL chaining (+2us); prefetch-before-gridsync.

#define B_  2
#define C_  64
#define D_  64
#define H_  96
#define W_  96
#define DHW_ 589824
#define NBC 128
#define NF4 (DHW_ / 4)              // 147456 float4 per (b,c) slab
#define NEG_SLOPE 0.01f

#define SPLIT 32                    // bulk parts per slab
#define F4_PER_PART (NF4 / SPLIT)   // 4608
#define THREADS 256
#define ITERS (F4_PER_PART / THREADS) // 18

#define NBND (NBC * 2)              // 2 boundary blocks per slab
#define NBLK (NBND + NBC * SPLIT)

#define SC_SPLIT 36
#define SC_THREADS 256
#define SC_ITERS (NF4 / SC_SPLIT / SC_THREADS) // 16
#define SC_PRE 6

__device__ float g_T [NBC * SPLIT];
__device__ float g_W0[NBC * SPLIT];
__device__ float g_WL[NBC * SPLIT];
__device__ float g_bnd[NBC * 24];
__device__ float g_gate[NBC];

// g_bnd layout per slab:
//  0:E_d0h0 1:E_d0hL 2:E_dLh0 3:E_dLhL   4:E_d0w0 5:E_d0wL 6:E_dLw0 7:E_dLwL
//  8:E_h0w0 9:E_h0wL 10:E_hLw0 11:E_hLwL
// 12..19: corners d0h0w0,d0h0wL,d0hLw0,d0hLwL,dLh0w0,dLh0wL,dLhLw0,dLhLwL
// 20:S_d0 21:S_dL 22:F_h0 23:F_hL

__device__ __forceinline__ void addf32x2(unsigned long long& a, unsigned long long b) {
    asm("add.rn.f32x2 %0, %0, %1;" : "+l"(a) : "l"(b));
}
__device__ __forceinline__ void mulf32x2(unsigned long long& a, unsigned long long b) {
    asm("mul.rn.f32x2 %0, %0, %1;" : "+l"(a) : "l"(b));
}
__device__ __forceinline__ float f32lo(unsigned long long v) {
    return __uint_as_float((unsigned)(v & 0xffffffffull));
}
__device__ __forceinline__ float f32hi(unsigned long long v) {
    return __uint_as_float((unsigned)(v >> 32));
}
__device__ __forceinline__ ulonglong2 ldnc_u64x2(const ulonglong2* p) {
    ulonglong2 v;
    asm("ld.global.nc.v2.u64 {%0,%1}, [%2];" : "=l"(v.x), "=l"(v.y) : "l"(p));
    return v;
}
__device__ __forceinline__ void stcs_u64x2(ulonglong2* p, ulonglong2 v) {
    asm("st.global.cs.v2.u64 [%0], {%1,%2};" :: "l"(p), "l"(v.x), "l"(v.y) : "memory");
}

// ================= Pass A: reduce (bulk + boundary blocks) =================
__global__ __launch_bounds__(THREADS, 8)
void fused_reduce(const float* __restrict__ x) {
    const int tid = threadIdx.x;
    __shared__ float warp_s[8 * 3];
    __shared__ float bsum[24];

    if (blockIdx.x >= NBND) {
        // ---------- bulk block: plain sum + w-column sums ----------
        const int bid  = blockIdx.x - NBND;
        const int slab = bid / SPLIT;
        const int part = bid % SPLIT;
        const ulonglong2* xp =
            (const ulonglong2*)x + (size_t)slab * NF4 + part * F4_PER_PART + tid;

        float mw0[3], mwL[3];
#pragma unroll
        for (int r = 0; r < 3; ++r) {
            int off = (tid + 16 * r) % 24;
            mw0[r] = (off == 0)  ? 1.0f : 0.0f;
            mwL[r] = (off == 23) ? 1.0f : 0.0f;
        }

        unsigned long long a01 = 0ull, a23 = 0ull;
        float w0acc = 0.f, wLacc = 0.f;
#pragma unroll
        for (int it = 0; it < ITERS; ++it) {
            ulonglong2 v = ldnc_u64x2(xp + it * THREADS);
            addf32x2(a01, v.x);
            addf32x2(a23, v.y);
            w0acc = fmaf(f32lo(v.x), mw0[it % 3], w0acc);
            wLacc = fmaf(f32hi(v.y), mwL[it % 3], wLacc);
        }
        float T = (f32lo(a01) + f32hi(a01)) + (f32lo(a23) + f32hi(a23));

        const int lane = tid & 31, wid = tid >> 5;
#pragma unroll
        for (int o = 16; o > 0; o >>= 1) {
            T     += __shfl_down_sync(0xFFFFFFFFu, T, o);
            w0acc += __shfl_down_sync(0xFFFFFFFFu, w0acc, o);
            wLacc += __shfl_down_sync(0xFFFFFFFFu, wLacc, o);
        }
        if (lane == 0) {
            warp_s[wid * 3 + 0] = T;
            warp_s[wid * 3 + 1] = w0acc;
            warp_s[wid * 3 + 2] = wLacc;
        }
        __syncthreads();
        if (tid == 0) {
            float t = 0.f, a = 0.f, b = 0.f;
#pragma unroll
            for (int w = 0; w < 8; ++w) {
                t += warp_s[w * 3 + 0];
                a += warp_s[w * 3 + 1];
                b += warp_s[w * 3 + 2];
            }
            g_T [slab * SPLIT + part] = t;
            g_W0[slab * SPLIT + part] = a;
            g_WL[slab * SPLIT + part] = b;
        }
        return;
    }

    // ---------- boundary blocks: 2 per slab ----------
    const int slab = blockIdx.x >> 1;
    const int typ  = blockIdx.x & 1;       // 0: d-faces, 1: h-faces
    const float4* xs = (const float4*)x + (size_t)slab * NF4;

    if (tid < 24) bsum[tid] = 0.f;
    __syncthreads();

    if (typ == 0) {
        // d-faces: full 96x96 planes at d=0 and d=63 (2304 f4 each)
        float s_d0 = 0.f, s_dL = 0.f;
#pragma unroll
        for (int p = 0; p < 2; ++p) {
            const float4* pb = xs + (p ? 63 * 2304 : 0);
            float sp = 0.f;
            for (int i = 0; i < 9; ++i) {
                int idx = i * 256 + tid;
                float4 v = __ldg(pb + idx);
                int h = idx / 24, w4 = idx - h * 24;
                float s4 = (v.x + v.y) + (v.z + v.w);
                sp += s4;
                bool h0 = (h == 0), hL = (h == 95);
                if (h0) atomicAdd(&bsum[p ? 2 : 0], s4);
                if (hL) atomicAdd(&bsum[p ? 3 : 1], s4);
                if (w4 == 0) {
                    atomicAdd(&bsum[p ? 6 : 4], v.x);
                    if (h0) atomicAdd(&bsum[12 + p * 4 + 0], v.x);
                    if (hL) atomicAdd(&bsum[12 + p * 4 + 2], v.x);
                }
                if (w4 == 23) {
                    atomicAdd(&bsum[p ? 7 : 5], v.w);
                    if (h0) atomicAdd(&bsum[12 + p * 4 + 1], v.w);
                    if (hL) atomicAdd(&bsum[12 + p * 4 + 3], v.w);
                }
            }
            if (p) s_dL = sp; else s_d0 = sp;
        }
#pragma unroll
        for (int o = 16; o > 0; o >>= 1) {
            s_d0 += __shfl_down_sync(0xFFFFFFFFu, s_d0, o);
            s_dL += __shfl_down_sync(0xFFFFFFFFu, s_dL, o);
        }
        if ((tid & 31) == 0) {
            atomicAdd(&bsum[20], s_d0);
            atomicAdd(&bsum[21], s_dL);
        }
        __syncthreads();
        if (tid < 22 && tid != 8 && tid != 9 && tid != 10 && tid != 11)
            g_bnd[slab * 24 + tid] = bsum[tid];
    } else {
        // h-faces: rows h=0 / h=95 for all d (1536 f4 each)
        float f_h0 = 0.f, f_hL = 0.f;
#pragma unroll
        for (int q = 0; q < 2; ++q) {
            float fq = 0.f;
            for (int i = 0; i < 6; ++i) {
                int idx = i * 256 + tid;
                int d = idx / 24, w4 = idx - d * 24;
                float4 v = __ldg(xs + d * 2304 + (q ? 2280 : 0) + w4);
                fq += (v.x + v.y) + (v.z + v.w);
                if (w4 == 0)  atomicAdd(&bsum[8 + 2 * q], v.x);
                if (w4 == 23) atomicAdd(&bsum[9 + 2 * q], v.w);
            }
            if (q) f_hL = fq; else f_h0 = fq;
        }
#pragma unroll
        for (int o = 16; o > 0; o >>= 1) {
            f_h0 += __shfl_down_sync(0xFFFFFFFFu, f_h0, o);
            f_hL += __shfl_down_sync(0xFFFFFFFFu, f_hL, o);
        }
        if ((tid & 31) == 0) {
            atomicAdd(&bsum[22], f_h0);
            atomicAdd(&bsum[23], f_hL);
        }
        __syncthreads();
        if ((tid >= 8 && tid < 12) || tid == 22 || tid == 23)
            g_bnd[slab * 24 + tid] = bsum[tid];
    }
}

// ================= Pass B: combine sums + MLP + sigmoid gate (PDL) =================
__global__ __launch_bounds__(128)
void mlp_kernel(const float* __restrict__ dw_w,
                const float* __restrict__ fc1_w,
                const float* __restrict__ fc1_b,
                const float* __restrict__ fc2_w,
                const float* __restrict__ fc2_b) {
    const int tid = threadIdx.x;        // tid == slab == b*64 + c
    const int c = tid & (C_ - 1);
    __shared__ float z_s[NBC];
    __shared__ float h_s[B_ * 8];

    // dependency-free preamble: load the small weights while reduce drains
    const float* wc = dw_w + c * 27;
    float w[27];
#pragma unroll
    for (int t = 0; t < 27; ++t) w[t] = wc[t];

    float Wall = 0.f;
    float Wd[3] = {0,0,0}, Wh[3] = {0,0,0}, Ww[3] = {0,0,0};
    float Wdh[3][3] = {}, Wdw[3][3] = {}, Whw[3][3] = {};
#pragma unroll
    for (int kd = 0; kd < 3; ++kd)
#pragma unroll
        for (int kh = 0; kh < 3; ++kh)
#pragma unroll
            for (int kw = 0; kw < 3; ++kw) {
                float v = w[kd * 9 + kh * 3 + kw];
                Wall += v;
                Wd[kd] += v; Wh[kh] += v; Ww[kw] += v;
                Wdh[kd][kh] += v; Wdw[kd][kw] += v; Whw[kh][kw] += v;
            }
    const float b1 = (tid < B_ * 8) ? fc1_b[tid % 8] : 0.f;
    float w1row[C_ / 4][4];
    if (tid < B_ * 8) {
        const int i = tid % 8;
#pragma unroll
        for (int cc = 0; cc < C_ / 4; ++cc) {
            float4 v = __ldg((const float4*)(fc1_w + i * C_) + cc);
            w1row[cc][0] = v.x; w1row[cc][1] = v.y;
            w1row[cc][2] = v.z; w1row[cc][3] = v.w;
        }
    }
    const float b2 = fc2_b[c];
    float w2row[8];
#pragma unroll
    for (int i = 0; i < 8; ++i) w2row[i] = fc2_w[c * 8 + i];

    // wait for fused_reduce results
    cudaGridDependencySynchronize();

    float T = 0.f, Fw0 = 0.f, FwL = 0.f;
#pragma unroll
    for (int p = 0; p < SPLIT; ++p) {
        T   += g_T [tid * SPLIT + p];
        Fw0 += g_W0[tid * SPLIT + p];
        FwL += g_WL[tid * SPLIT + p];
    }
    float bv[24];
#pragma unroll
    for (int k = 0; k < 24; ++k) bv[k] = g_bnd[tid * 24 + k];

    float zs = Wall * T
        - Wd[2] * bv[20] - Wd[0] * bv[21]
        - Wh[2] * bv[22] - Wh[0] * bv[23]
        - Ww[2] * Fw0    - Ww[0] * FwL
        + Wdh[2][2]*bv[0] + Wdh[2][0]*bv[1] + Wdh[0][2]*bv[2] + Wdh[0][0]*bv[3]
        + Wdw[2][2]*bv[4] + Wdw[2][0]*bv[5] + Wdw[0][2]*bv[6] + Wdw[0][0]*bv[7]
        + Whw[2][2]*bv[8] + Whw[2][0]*bv[9] + Whw[0][2]*bv[10] + Whw[0][0]*bv[11]
        - w[26]*bv[12] - w[24]*bv[13] - w[20]*bv[14] - w[18]*bv[15]
        - w[8] *bv[16] - w[6] *bv[17] - w[2] *bv[18] - w[0] *bv[19];

    z_s[tid] = zs * (1.0f / (float)DHW_);
    __syncthreads();

    if (tid < B_ * 8) {
        const int b = tid / 8;
        float h = b1;
#pragma unroll
        for (int cc = 0; cc < C_ / 4; ++cc)
#pragma unroll
            for (int j = 0; j < 4; ++j)
                h += z_s[b * C_ + cc * 4 + j] * w1row[cc][j];
        h_s[tid] = (h >= 0.f) ? h : NEG_SLOPE * h;
    }
    __syncthreads();

    const int b = tid / C_;
    float g = b2;
#pragma unroll
    for (int i = 0; i < 8; ++i)
        g += h_s[b * 8 + i] * w2row[i];
    g_gate[tid] = 1.0f / (1.0f + __expf(-g));
    // release downstream (scale) as soon as the gate is written
    cudaTriggerProgrammaticLaunchCompletion();
}

// ===== Pass C: out = x * gate — reversed, .cs stores, prefetch-before-sync =====
__global__ __launch_bounds__(SC_THREADS)
void scale_kernel(const float* __restrict__ x, float* __restrict__ out) {
    const int rb   = (NBC * SC_SPLIT - 1) - blockIdx.x;  // descending addresses
    const int slab = rb / SC_SPLIT;
    const int sub  = rb % SC_SPLIT;

    const size_t base = (size_t)slab * NF4 + (size_t)sub * (NF4 / SC_SPLIT) + threadIdx.x;
    const ulonglong2* xp = (const ulonglong2*)x + base;
    ulonglong2*       op = (ulonglong2*)out + base;

    // x loads don't depend on the gate: prefetch to hide the mlp wait.
    ulonglong2 pre[SC_PRE];
#pragma unroll
    for (int it = 0; it < SC_PRE; ++it)
        pre[it] = ldnc_u64x2(xp + it * SC_THREADS);

    cudaGridDependencySynchronize();

    const float g = g_gate[slab];
    unsigned long long gg;
    asm("mov.b64 %0, {%1,%1};" : "=l"(gg) : "r"(__float_as_uint(g)));

#pragma unroll
    for (int it = 0; it < SC_PRE; ++it) {
        ulonglong2 v = pre[it];
        mulf32x2(v.x, gg);
        mulf32x2(v.y, gg);
        stcs_u64x2(op + it * SC_THREADS, v);
    }
#pragma unroll
    for (int it = SC_PRE; it < SC_ITERS; ++it) {
        ulonglong2 v = ldnc_u64x2(xp + it * SC_THREADS);
        mulf32x2(v.x, gg);
        mulf32x2(v.y, gg);
        stcs_u64x2(op + it * SC_THREADS, v);
    }
}

extern "C" void kernel_launch(void* const* d_in, const int* in_sizes, int n_in,
                              void* d_out, int out_size) {
    const float* x     = (const float*)d_in[0];
    const float* dw_w  = (const float*)d_in[1];
    const float* fc1_w = (const float*)d_in[2];
    const float* fc1_b = (const float*)d_in[3];
    const float* fc2_w = (const float*)d_in[4];
    const float* fc2_b = (const float*)d_in[5];
    float* out = (float*)d_out;

    cudaLaunchAttribute attr[1];
    attr[0].id = cudaLaunchAttributeProgrammaticStreamSerialization;
    attr[0].val.programmaticStreamSerializationAllowed = 1;

    {
        cudaLaunchConfig_t cfg = {};
        cfg.gridDim = dim3(NBLK, 1, 1);
        cfg.blockDim = dim3(THREADS, 1, 1);
        cfg.attrs = attr;
        cfg.numAttrs = 1;
        cudaLaunchKernelEx(&cfg, fused_reduce, x);
    }
    {
        cudaLaunchConfig_t cfg = {};
        cfg.gridDim = dim3(1, 1, 1);
        cfg.blockDim = dim3(128, 1, 1);
        cfg.attrs = attr;
        cfg.numAttrs = 1;
        cudaLaunchKernelEx(&cfg, mlp_kernel, dw_w, fc1_w, fc1_b, fc2_w, fc2_b);
    }
    {
        cudaLaunchConfig_t cfg = {};
        cfg.gridDim = dim3(NBC * SC_SPLIT, 1, 1);
        cfg.blockDim = dim3(SC_THREADS, 1, 1);
        cfg.attrs = attr;
        cfg.numAttrs = 1;
        cudaLaunchKernelEx(&cfg, scale_kernel, x, out);
    }
}